// round 1
// baseline (speedup 1.0000x reference)
#include <cuda_runtime.h>
#include <math.h>

// SSIM loss, fused single-pass: separable 11x11 Gaussian depthwise conv on
// clip(x), clip(y), x^2, y^2, x*y + per-pixel SSIM + global mean reduction.
// Tile 32x32 per block, halo 5. Vertical pass produces a 5-channel
// intermediate in SMEM; horizontal pass consumes it 4 outputs/thread.

#define TW 32
#define TH 32
#define HALO 5
#define KS 11
#define HW (TW + 2 * HALO)   // 42
#define HH (TH + 2 * HALO)   // 42
#define SW 45                // shared row stride (odd*... 13 mod 32 -> conflict-free)

__device__ double g_acc;

__global__ void ssim_init_k() { g_acc = 0.0; }

__global__ void ssim_fin_k(float* __restrict__ out) {
    out[0] = 1.0f - (float)(g_acc / 25165824.0);  // 32*3*512*512
}

__global__ __launch_bounds__(256, 2)
void ssim_main_k(const float* __restrict__ A, const float* __restrict__ Bp) {
    __shared__ float sx[HH][SW];
    __shared__ float sy[HH][SW];
    __shared__ float sv[5][TH][SW];
    __shared__ float red[8];

    const int tid = threadIdx.x;
    const int tx0 = blockIdx.x * TW;
    const int ty0 = blockIdx.y * TH;
    const size_t base = (size_t)blockIdx.z * (512 * 512);

    // Gaussian weights (sigma=1.5), computed per-thread; unrolled const-index use.
    float w[KS];
    {
        float s = 0.f;
#pragma unroll
        for (int i = 0; i < KS; i++) {
            float d = (float)(i - 5);
            w[i] = expf(-d * d * (1.0f / 4.5f));
            s += w[i];
        }
        float inv = 1.0f / s;
#pragma unroll
        for (int i = 0; i < KS; i++) w[i] *= inv;
    }

    // -------- Phase 1: load halo tile (clip to [0,1], zero outside image) ----
    for (int i = tid; i < HH * HW; i += 256) {
        int r = i / HW, c = i - r * HW;
        int gy = ty0 + r - HALO, gx = tx0 + c - HALO;
        float xv = 0.f, yv = 0.f;
        if ((unsigned)gy < 512u && (unsigned)gx < 512u) {
            size_t idx = base + (size_t)gy * 512 + gx;
            xv = __ldg(A + idx);
            yv = __ldg(Bp + idx);
            xv = fminf(fmaxf(xv, 0.f), 1.f);
            yv = fminf(fmaxf(yv, 0.f), 1.f);
        }
        sx[r][c] = xv;
        sy[r][c] = yv;
    }
    __syncthreads();

    // -------- Phase 2: vertical conv; each item = 4 consecutive output rows,
    // one halo column. items = 8 rowgroups * 42 cols = 336.
    for (int i = tid; i < 8 * HW; i += 256) {
        int g = i / HW, ch = i - g * HW;
        int r0 = g * 4;
        float ax[4] = {0, 0, 0, 0}, ay[4] = {0, 0, 0, 0};
        float axx[4] = {0, 0, 0, 0}, ayy[4] = {0, 0, 0, 0}, axy[4] = {0, 0, 0, 0};
#pragma unroll
        for (int p = 0; p < 14; p++) {
            float xv = sx[r0 + p][ch];
            float yv = sy[r0 + p][ch];
#pragma unroll
            for (int o = 0; o < 4; o++) {
                int j = p - o;
                if (j >= 0 && j < KS) {
                    float wj = w[j];
                    float wx = wj * xv;
                    float wy = wj * yv;
                    ax[o] += wx;
                    ay[o] += wy;
                    axx[o] = fmaf(wx, xv, axx[o]);
                    ayy[o] = fmaf(wy, yv, ayy[o]);
                    axy[o] = fmaf(wx, yv, axy[o]);
                }
            }
        }
#pragma unroll
        for (int o = 0; o < 4; o++) {
            sv[0][r0 + o][ch] = ax[o];
            sv[1][r0 + o][ch] = ay[o];
            sv[2][r0 + o][ch] = axx[o];
            sv[3][r0 + o][ch] = ayy[o];
            sv[4][r0 + o][ch] = axy[o];
        }
    }
    __syncthreads();

    // -------- Phase 3: horizontal conv + SSIM; each thread = 4 consecutive
    // output columns of one row. 32 rows * 8 colgroups = 256 items.
    float lsum = 0.f;
    {
        const int r = tid >> 3;
        const int c0 = (tid & 7) * 4;
        float ax[4] = {0, 0, 0, 0}, ay[4] = {0, 0, 0, 0};
        float axx[4] = {0, 0, 0, 0}, ayy[4] = {0, 0, 0, 0}, axy[4] = {0, 0, 0, 0};
#pragma unroll
        for (int p = 0; p < 14; p++) {
            float vX  = sv[0][r][c0 + p];
            float vY  = sv[1][r][c0 + p];
            float vXX = sv[2][r][c0 + p];
            float vYY = sv[3][r][c0 + p];
            float vXY = sv[4][r][c0 + p];
#pragma unroll
            for (int o = 0; o < 4; o++) {
                int j = p - o;
                if (j >= 0 && j < KS) {
                    float wj = w[j];
                    ax[o]  = fmaf(wj, vX,  ax[o]);
                    ay[o]  = fmaf(wj, vY,  ay[o]);
                    axx[o] = fmaf(wj, vXX, axx[o]);
                    ayy[o] = fmaf(wj, vYY, ayy[o]);
                    axy[o] = fmaf(wj, vXY, axy[o]);
                }
            }
        }
        const float C1 = 1e-4f;   // 0.01^2
        const float C2 = 9e-4f;   // 0.03^2
#pragma unroll
        for (int o = 0; o < 4; o++) {
            float mu1 = ax[o], mu2 = ay[o];
            float mu1sq = mu1 * mu1;
            float mu2sq = mu2 * mu2;
            float mu12  = mu1 * mu2;
            float s1  = axx[o] - mu1sq;
            float s2  = ayy[o] - mu2sq;
            float s12 = axy[o] - mu12;
            float num = (2.f * mu12 + C1) * (2.f * s12 + C2);
            float den = (mu1sq + mu2sq + C1) * (s1 + s2 + C2);
            lsum += __fdividef(num, den);
        }
    }

    // -------- Block reduction -> one double atomic per block ----------------
#pragma unroll
    for (int off = 16; off; off >>= 1)
        lsum += __shfl_xor_sync(0xffffffffu, lsum, off);
    if ((tid & 31) == 0) red[tid >> 5] = lsum;
    __syncthreads();
    if (tid == 0) {
        float s = 0.f;
#pragma unroll
        for (int i = 0; i < 8; i++) s += red[i];
        atomicAdd(&g_acc, (double)s);
    }
}

extern "C" void kernel_launch(void* const* d_in, const int* in_sizes, int n_in,
                              void* d_out, int out_size) {
    const float* A = (const float*)d_in[0];   // denoised
    const float* B = (const float*)d_in[1];   // clean
    float* out = (float*)d_out;

    ssim_init_k<<<1, 1>>>();
    dim3 grid(512 / TW, 512 / TH, 32 * 3);    // (16, 16, 96)
    ssim_main_k<<<grid, 256>>>(A, B);
    ssim_fin_k<<<1, 1>>>(out);
}

// round 2
// speedup vs baseline: 1.0496x; 1.0496x over previous
#include <cuda_runtime.h>

// SSIM loss, fused single kernel: clip -> separable 11x11 Gaussian depthwise
// conv of (x, y, x^2, y^2, xy) -> SSIM map -> global mean, one launch.
// Tile 32x32 + halo 5. Weights are compile-time literals so ptxas can emit
// FFMA-imm (rt=1). Phase-3 horizontal conv loads its window with LDS.128.

#define TW 32
#define TH 32
#define HALO 5
#define KS 11
#define HWD 42            // TW + 2*HALO
#define HHT 42            // TH + 2*HALO
#define SW 48             // shared row stride (16B-aligned float4 rows)

__device__ double g_acc = 0.0;
__device__ unsigned int g_cnt = 0;

// Gaussian(sigma=1.5), normalized, precomputed in double, hardcoded.
__device__ constexpr float GW[11] = {
    0.00102838f, 0.00759876f, 0.03600078f, 0.10936069f, 0.21300553f,
    0.26601173f,
    0.21300553f, 0.10936069f, 0.03600078f, 0.00759876f, 0.00102838f};

__global__ __launch_bounds__(256, 3)
void ssim_main_k(const float* __restrict__ A, const float* __restrict__ Bp,
                 float* __restrict__ out) {
    __shared__ __align__(16) float sx[HHT][SW];
    __shared__ __align__(16) float sy[HHT][SW];
    __shared__ __align__(16) float sv[5][TH][SW];
    __shared__ float red[8];

    const int tid = threadIdx.x;
    const int tx0 = blockIdx.x * TW;
    const int ty0 = blockIdx.y * TH;
    const size_t base = (size_t)blockIdx.z * (512 * 512);

    // -------- Phase 1: load halo tile, clip to [0,1], zero outside ----------
    for (int i = tid; i < HHT * HWD; i += 256) {
        int r = i / HWD, c = i - r * HWD;
        int gy = ty0 + r - HALO, gx = tx0 + c - HALO;
        float xv = 0.f, yv = 0.f;
        if ((unsigned)gy < 512u && (unsigned)gx < 512u) {
            size_t idx = base + (size_t)gy * 512 + gx;
            xv = __ldg(A + idx);
            yv = __ldg(Bp + idx);
            xv = fminf(fmaxf(xv, 0.f), 1.f);
            yv = fminf(fmaxf(yv, 0.f), 1.f);
        }
        sx[r][c] = xv;
        sy[r][c] = yv;
    }
    __syncthreads();

    // -------- Phase 2: vertical conv, 4 output rows per item ----------------
    // items = 8 rowgroups * 42 cols = 336
    for (int i = tid; i < 8 * HWD; i += 256) {
        int g = i / HWD, ch = i - g * HWD;
        int r0 = g * 4;
        float ax[4] = {0, 0, 0, 0}, ay[4] = {0, 0, 0, 0};
        float axx[4] = {0, 0, 0, 0}, ayy[4] = {0, 0, 0, 0}, axy[4] = {0, 0, 0, 0};
#pragma unroll
        for (int p = 0; p < 14; p++) {
            float xv = sx[r0 + p][ch];
            float yv = sy[r0 + p][ch];
            float xx = xv * xv;
            float yy = yv * yv;
            float xy = xv * yv;
#pragma unroll
            for (int o = 0; o < 4; o++) {
                int j = p - o;
                if (j >= 0 && j < KS) {
                    float wj = GW[j];              // compile-time literal
                    ax[o]  = fmaf(wj, xv, ax[o]);
                    ay[o]  = fmaf(wj, yv, ay[o]);
                    axx[o] = fmaf(wj, xx, axx[o]);
                    ayy[o] = fmaf(wj, yy, ayy[o]);
                    axy[o] = fmaf(wj, xy, axy[o]);
                }
            }
        }
#pragma unroll
        for (int o = 0; o < 4; o++) {
            sv[0][r0 + o][ch] = ax[o];
            sv[1][r0 + o][ch] = ay[o];
            sv[2][r0 + o][ch] = axx[o];
            sv[3][r0 + o][ch] = ayy[o];
            sv[4][r0 + o][ch] = axy[o];
        }
    }
    __syncthreads();

    // -------- Phase 3: horizontal conv (LDS.128 window) + SSIM --------------
    float lsum = 0.f;
    {
        const int r = tid >> 3;
        const int c0 = (tid & 7) * 4;
        float accv[5][4];
#pragma unroll
        for (int chn = 0; chn < 5; chn++) {
            const float* rp = &sv[chn][r][c0];     // 16B aligned (SW%4==0, c0%4==0)
            float4 q0 = *(const float4*)(rp);
            float4 q1 = *(const float4*)(rp + 4);
            float4 q2 = *(const float4*)(rp + 8);
            float4 q3 = *(const float4*)(rp + 12);
            float v[16] = {q0.x, q0.y, q0.z, q0.w, q1.x, q1.y, q1.z, q1.w,
                           q2.x, q2.y, q2.z, q2.w, q3.x, q3.y, q3.z, q3.w};
#pragma unroll
            for (int o = 0; o < 4; o++) {
                float s = 0.f;
#pragma unroll
                for (int j = 0; j < KS; j++)
                    s = fmaf(GW[j], v[o + j], s);   // FFMA-imm
                accv[chn][o] = s;
            }
        }
        const float C1 = 1e-4f;
        const float C2 = 9e-4f;
#pragma unroll
        for (int o = 0; o < 4; o++) {
            float mu1 = accv[0][o], mu2 = accv[1][o];
            float mu1sq = mu1 * mu1;
            float mu2sq = mu2 * mu2;
            float mu12  = mu1 * mu2;
            float s1  = accv[2][o] - mu1sq;
            float s2  = accv[3][o] - mu2sq;
            float s12 = accv[4][o] - mu12;
            float num = (2.f * mu12 + C1) * (2.f * s12 + C2);
            float den = (mu1sq + mu2sq + C1) * (s1 + s2 + C2);
            lsum += __fdividef(num, den);
        }
    }

    // -------- Block reduce -> atomic; last block finalizes ------------------
#pragma unroll
    for (int off = 16; off; off >>= 1)
        lsum += __shfl_xor_sync(0xffffffffu, lsum, off);
    if ((tid & 31) == 0) red[tid >> 5] = lsum;
    __syncthreads();
    if (tid == 0) {
        float s = 0.f;
#pragma unroll
        for (int i = 0; i < 8; i++) s += red[i];
        atomicAdd(&g_acc, (double)s);
        __threadfence();
        unsigned int total = gridDim.x * gridDim.y * gridDim.z;
        unsigned int old = atomicAdd(&g_cnt, 1u);
        if (old == total - 1u) {
            double tot = atomicAdd(&g_acc, 0.0);   // coherent L2 read
            out[0] = 1.0f - (float)(tot / 25165824.0);  // 32*3*512*512
            g_acc = 0.0;                           // reset for next replay
            __threadfence();
            g_cnt = 0;
        }
    }
}

extern "C" void kernel_launch(void* const* d_in, const int* in_sizes, int n_in,
                              void* d_out, int out_size) {
    const float* A = (const float*)d_in[0];   // denoised
    const float* B = (const float*)d_in[1];   // clean
    float* out = (float*)d_out;

    dim3 grid(512 / TW, 512 / TH, 32 * 3);    // (16, 16, 96)
    ssim_main_k<<<grid, 256>>>(A, B, out);
}

// round 3
// speedup vs baseline: 1.3128x; 1.2507x over previous
#include <cuda_runtime.h>

// SSIM loss, fused single kernel, f32x2-packed separable 11x11 Gaussian conv.
// Phase 1: halo tile load + clip. Phase 2: vertical conv of (x,y,xx,yy,xy),
// column-pair packed (FFMA2). Phase 3: horizontal conv on packed pairs +
// packed SSIM + global mean reduction.

#define TW 32
#define TH 32
#define HALO 5
#define KS 11
#define HWD 42
#define SWX 48            // sx/sy row stride (floats)
#define S2  22            // sv2 row stride (u64 elems; 11 granules, odd -> conflict-free LDS.128)

typedef unsigned long long u64t;

__device__ double g_acc = 0.0;
__device__ unsigned int g_cnt = 0;

__device__ constexpr float GW[11] = {
    0.00102838f, 0.00759876f, 0.03600078f, 0.10936069f, 0.21300553f,
    0.26601173f,
    0.21300553f, 0.10936069f, 0.03600078f, 0.00759876f, 0.00102838f};

__device__ __forceinline__ u64t pk2(float lo, float hi) {
    u64t r; asm("mov.b64 %0,{%1,%2};" : "=l"(r) : "f"(lo), "f"(hi)); return r;
}
__device__ __forceinline__ void upk2(u64t v, float& lo, float& hi) {
    asm("mov.b64 {%0,%1},%2;" : "=f"(lo), "=f"(hi) : "l"(v));
}
__device__ __forceinline__ u64t fma2_(u64t a, u64t b, u64t c) {
    u64t d; asm("fma.rn.f32x2 %0,%1,%2,%3;" : "=l"(d) : "l"(a), "l"(b), "l"(c)); return d;
}
__device__ __forceinline__ u64t mul2_(u64t a, u64t b) {
    u64t d; asm("mul.rn.f32x2 %0,%1,%2;" : "=l"(d) : "l"(a), "l"(b)); return d;
}
__device__ __forceinline__ u64t add2_(u64t a, u64t b) {
    u64t d; asm("add.rn.f32x2 %0,%1,%2;" : "=l"(d) : "l"(a), "l"(b)); return d;
}
__device__ __forceinline__ u64t sub2_(u64t a, u64t b) {
    u64t d; asm("sub.rn.f32x2 %0,%1,%2;" : "=l"(d) : "l"(a), "l"(b)); return d;
}

// weight symmetry: 6 distinct values
__device__ __forceinline__ constexpr int WS(int j) { return j < 6 ? j : 10 - j; }

__global__ __launch_bounds__(256, 2)
void ssim_main_k(const float* __restrict__ A, const float* __restrict__ Bp,
                 float* __restrict__ out) {
    __shared__ __align__(16) float sx[HWD][SWX];
    __shared__ __align__(16) float sy[HWD][SWX];
    __shared__ __align__(16) u64t  sv2[5][TH][S2];
    __shared__ float red[8];

    const int tid = threadIdx.x;
    const int tx0 = blockIdx.x * TW;
    const int ty0 = blockIdx.y * TH;
    const size_t base = (size_t)blockIdx.z * (512 * 512);

    // packed (w, w) weights, 6 distinct
    u64t wq[6];
#pragma unroll
    for (int j = 0; j < 6; j++) wq[j] = pk2(GW[j], GW[j]);

    // -------- Phase 1: halo tile load, clip, zero outside -------------------
    const bool interior = (blockIdx.x != 0) && (blockIdx.x != 15) &&
                          (blockIdx.y != 0) && (blockIdx.y != 15);
    if (interior) {
#pragma unroll
        for (int i = tid; i < HWD * HWD; i += 256) {
            int r = i / HWD, c = i - r * HWD;
            size_t idx = base + (size_t)(ty0 + r - HALO) * 512 + (tx0 + c - HALO);
            sx[r][c] = __saturatef(__ldg(A + idx));
            sy[r][c] = __saturatef(__ldg(Bp + idx));
        }
    } else {
#pragma unroll
        for (int i = tid; i < HWD * HWD; i += 256) {
            int r = i / HWD, c = i - r * HWD;
            int gy = ty0 + r - HALO, gx = tx0 + c - HALO;
            float xv = 0.f, yv = 0.f;
            if ((unsigned)gy < 512u && (unsigned)gx < 512u) {
                size_t idx = base + (size_t)gy * 512 + gx;
                xv = __saturatef(__ldg(A + idx));
                yv = __saturatef(__ldg(Bp + idx));
            }
            sx[r][c] = xv;
            sy[r][c] = yv;
        }
    }
    __syncthreads();

    // -------- Phase 2: vertical conv, col-pair packed ------------------------
    // 168 items = 8 rowgroups (4 rows each) x 21 packed col-pairs
    if (tid < 168) {
        const int g = tid / 21;
        const int k = tid - 21 * g;       // packed col pair (2k, 2k+1)
        const int r0 = g * 4;
        u64t ax[4] = {0,0,0,0}, ay[4] = {0,0,0,0};
        u64t axx[4] = {0,0,0,0}, ayy[4] = {0,0,0,0}, axy[4] = {0,0,0,0};
        const float* px = &sx[r0][2 * k];
        const float* py = &sy[r0][2 * k];
#pragma unroll
        for (int p = 0; p < 14; p++) {
            float2 xv = *(const float2*)(px + p * SWX);
            float2 yv = *(const float2*)(py + p * SWX);
            u64t X = pk2(xv.x, xv.y);
            u64t Y = pk2(yv.x, yv.y);
            u64t XX = mul2_(X, X);
            u64t YY = mul2_(Y, Y);
            u64t XY = mul2_(X, Y);
#pragma unroll
            for (int o = 0; o < 4; o++) {
                int j = p - o;
                if (j >= 0 && j < KS) {
                    u64t w = wq[WS(j)];
                    ax[o]  = fma2_(w, X,  ax[o]);
                    ay[o]  = fma2_(w, Y,  ay[o]);
                    axx[o] = fma2_(w, XX, axx[o]);
                    ayy[o] = fma2_(w, YY, ayy[o]);
                    axy[o] = fma2_(w, XY, axy[o]);
                }
            }
        }
#pragma unroll
        for (int o = 0; o < 4; o++) {
            int row = r0 + o;
            sv2[0][row][k] = ax[o];
            sv2[1][row][k] = ay[o];
            sv2[2][row][k] = axx[o];
            sv2[3][row][k] = ayy[o];
            sv2[4][row][k] = axy[o];
        }
    }
    __syncthreads();

    // -------- Phase 3: horizontal conv on packed pairs + SSIM ----------------
    // 128 items = 32 rows x 4 colgroups (8 output cols each = 4 packed outs)
    float lsum = 0.f;
    if (tid < 128) {
        const int r  = tid >> 2;
        const int cg = tid & 3;
        const int m0 = 4 * cg;            // first packed output elem
        u64t acc[5][4];
#pragma unroll
        for (int ch = 0; ch < 5; ch++) {
            const u64t* rowp = &sv2[ch][r][m0];
            // 9 packed elems E[0..8] (18 cols window), LDS.128 x4 + LDS.64
            u64t E[9];
            ulonglong2 q0 = *(const ulonglong2*)(rowp);
            ulonglong2 q1 = *(const ulonglong2*)(rowp + 2);
            ulonglong2 q2 = *(const ulonglong2*)(rowp + 4);
            ulonglong2 q3 = *(const ulonglong2*)(rowp + 6);
            E[0] = q0.x; E[1] = q0.y; E[2] = q1.x; E[3] = q1.y;
            E[4] = q2.x; E[5] = q2.y; E[6] = q3.x; E[7] = q3.y;
            E[8] = rowp[8];
            float flo[9], fhi[9];
#pragma unroll
            for (int t = 0; t < 9; t++) upk2(E[t], flo[t], fhi[t]);
            u64t O[8];
#pragma unroll
            for (int t = 0; t < 8; t++) O[t] = pk2(fhi[t], flo[t + 1]);
#pragma unroll
            for (int o = 0; o < 4; o++) {
                u64t a = mul2_(wq[WS(0)], E[o]);
#pragma unroll
                for (int j = 1; j < KS; j++) {
                    u64t v = (j & 1) ? O[o + (j - 1) / 2] : E[o + j / 2];
                    a = fma2_(wq[WS(j)], v, a);
                }
                acc[ch][o] = a;
            }
        }
        const u64t TWO = pk2(2.f, 2.f);
        const u64t C1q = pk2(1e-4f, 1e-4f);
        const u64t C2q = pk2(9e-4f, 9e-4f);
#pragma unroll
        for (int o = 0; o < 4; o++) {
            u64t mu1 = acc[0][o], mu2 = acc[1][o];
            u64t mu1sq = mul2_(mu1, mu1);
            u64t mu2sq = mul2_(mu2, mu2);
            u64t mu12  = mul2_(mu1, mu2);
            u64t s1  = sub2_(acc[2][o], mu1sq);
            u64t s2  = sub2_(acc[3][o], mu2sq);
            u64t s12 = sub2_(acc[4][o], mu12);
            u64t num = mul2_(fma2_(TWO, mu12, C1q), fma2_(TWO, s12, C2q));
            u64t den = mul2_(add2_(add2_(mu1sq, mu2sq), C1q),
                             add2_(add2_(s1, s2), C2q));
            float nlo, nhi, dlo, dhi;
            upk2(num, nlo, nhi);
            upk2(den, dlo, dhi);
            lsum += __fdividef(nlo, dlo) + __fdividef(nhi, dhi);
        }
    }

    // -------- Block reduce -> atomic; last block finalizes -------------------
#pragma unroll
    for (int off = 16; off; off >>= 1)
        lsum += __shfl_xor_sync(0xffffffffu, lsum, off);
    if ((tid & 31) == 0) red[tid >> 5] = lsum;
    __syncthreads();
    if (tid == 0) {
        float s = 0.f;
#pragma unroll
        for (int i = 0; i < 8; i++) s += red[i];
        atomicAdd(&g_acc, (double)s);
        __threadfence();
        unsigned int total = gridDim.x * gridDim.y * gridDim.z;
        unsigned int old = atomicAdd(&g_cnt, 1u);
        if (old == total - 1u) {
            double tot = atomicAdd(&g_acc, 0.0);
            out[0] = 1.0f - (float)(tot / 25165824.0);   // 32*3*512*512
            g_acc = 0.0;
            __threadfence();
            g_cnt = 0;
        }
    }
}

extern "C" void kernel_launch(void* const* d_in, const int* in_sizes, int n_in,
                              void* d_out, int out_size) {
    const float* A = (const float*)d_in[0];   // denoised
    const float* B = (const float*)d_in[1];   // clean
    float* out = (float*)d_out;

    dim3 grid(512 / TW, 512 / TH, 32 * 3);    // (16, 16, 96)
    ssim_main_k<<<grid, 256>>>(A, B, out);
}

// round 4
// speedup vs baseline: 1.3758x; 1.0480x over previous
#include <cuda_runtime.h>

// SSIM loss, fused single kernel, f32x2-packed separable 11x11 Gaussian conv.
// Phase 1: halo tile load + clip. Phase 2: vertical conv of (x,y,xx,yy,xy),
// column-pair packed (FFMA2), 168 items x 4 rows. Phase 3: horizontal conv,
// 256 items x 2 packed outputs (full thread utilization) + packed SSIM +
// global mean reduction.

#define TW 32
#define TH 32
#define HALO 5
#define KS 11
#define HWD 42
#define SWX 48            // sx/sy row stride (floats)
#define S2  22            // sv2 row stride (u64 elems)

typedef unsigned long long u64t;

__device__ double g_acc = 0.0;
__device__ unsigned int g_cnt = 0;

__device__ constexpr float GW[11] = {
    0.00102838f, 0.00759876f, 0.03600078f, 0.10936069f, 0.21300553f,
    0.26601173f,
    0.21300553f, 0.10936069f, 0.03600078f, 0.00759876f, 0.00102838f};

__device__ __forceinline__ u64t pk2(float lo, float hi) {
    u64t r; asm("mov.b64 %0,{%1,%2};" : "=l"(r) : "f"(lo), "f"(hi)); return r;
}
__device__ __forceinline__ void upk2(u64t v, float& lo, float& hi) {
    asm("mov.b64 {%0,%1},%2;" : "=f"(lo), "=f"(hi) : "l"(v));
}
__device__ __forceinline__ u64t fma2_(u64t a, u64t b, u64t c) {
    u64t d; asm("fma.rn.f32x2 %0,%1,%2,%3;" : "=l"(d) : "l"(a), "l"(b), "l"(c)); return d;
}
__device__ __forceinline__ u64t mul2_(u64t a, u64t b) {
    u64t d; asm("mul.rn.f32x2 %0,%1,%2;" : "=l"(d) : "l"(a), "l"(b)); return d;
}
__device__ __forceinline__ u64t add2_(u64t a, u64t b) {
    u64t d; asm("add.rn.f32x2 %0,%1,%2;" : "=l"(d) : "l"(a), "l"(b)); return d;
}
__device__ __forceinline__ u64t sub2_(u64t a, u64t b) {
    u64t d; asm("sub.rn.f32x2 %0,%1,%2;" : "=l"(d) : "l"(a), "l"(b)); return d;
}

__device__ __forceinline__ constexpr int WS(int j) { return j < 6 ? j : 10 - j; }

__global__ __launch_bounds__(256, 3)
void ssim_main_k(const float* __restrict__ A, const float* __restrict__ Bp,
                 float* __restrict__ out) {
    __shared__ __align__(16) float sx[HWD][SWX];
    __shared__ __align__(16) float sy[HWD][SWX];
    __shared__ __align__(16) u64t  sv2[5][TH][S2];
    __shared__ float red[8];

    const int tid = threadIdx.x;
    const int tx0 = blockIdx.x * TW;
    const int ty0 = blockIdx.y * TH;
    const size_t base = (size_t)blockIdx.z * (512 * 512);

    u64t wq[6];
#pragma unroll
    for (int j = 0; j < 6; j++) wq[j] = pk2(GW[j], GW[j]);

    // -------- Phase 1: halo tile load, clip, zero outside -------------------
    const bool interior = (blockIdx.x != 0) && (blockIdx.x != 15) &&
                          (blockIdx.y != 0) && (blockIdx.y != 15);
    if (interior) {
#pragma unroll
        for (int i = tid; i < HWD * HWD; i += 256) {
            int r = i / HWD, c = i - r * HWD;
            size_t idx = base + (size_t)(ty0 + r - HALO) * 512 + (tx0 + c - HALO);
            sx[r][c] = __saturatef(__ldg(A + idx));
            sy[r][c] = __saturatef(__ldg(Bp + idx));
        }
    } else {
#pragma unroll
        for (int i = tid; i < HWD * HWD; i += 256) {
            int r = i / HWD, c = i - r * HWD;
            int gy = ty0 + r - HALO, gx = tx0 + c - HALO;
            float xv = 0.f, yv = 0.f;
            if ((unsigned)gy < 512u && (unsigned)gx < 512u) {
                size_t idx = base + (size_t)gy * 512 + gx;
                xv = __saturatef(__ldg(A + idx));
                yv = __saturatef(__ldg(Bp + idx));
            }
            sx[r][c] = xv;
            sy[r][c] = yv;
        }
    }
    __syncthreads();

    // -------- Phase 2: vertical conv, col-pair packed ------------------------
    // 168 items = 8 rowgroups (4 rows each) x 21 packed col-pairs
    if (tid < 168) {
        const int g = tid / 21;
        const int k = tid - 21 * g;
        const int r0 = g * 4;
        u64t ax[4] = {0,0,0,0}, ay[4] = {0,0,0,0};
        u64t axx[4] = {0,0,0,0}, ayy[4] = {0,0,0,0}, axy[4] = {0,0,0,0};
        const float* px = &sx[r0][2 * k];
        const float* py = &sy[r0][2 * k];
#pragma unroll
        for (int p = 0; p < 14; p++) {
            float2 xv = *(const float2*)(px + p * SWX);
            float2 yv = *(const float2*)(py + p * SWX);
            u64t X = pk2(xv.x, xv.y);
            u64t Y = pk2(yv.x, yv.y);
            u64t XX = mul2_(X, X);
            u64t YY = mul2_(Y, Y);
            u64t XY = mul2_(X, Y);
#pragma unroll
            for (int o = 0; o < 4; o++) {
                int j = p - o;
                if (j >= 0 && j < KS) {
                    u64t w = wq[WS(j)];
                    ax[o]  = fma2_(w, X,  ax[o]);
                    ay[o]  = fma2_(w, Y,  ay[o]);
                    axx[o] = fma2_(w, XX, axx[o]);
                    ayy[o] = fma2_(w, YY, ayy[o]);
                    axy[o] = fma2_(w, XY, axy[o]);
                }
            }
        }
#pragma unroll
        for (int o = 0; o < 4; o++) {
            int row = r0 + o;
            sv2[0][row][k] = ax[o];
            sv2[1][row][k] = ay[o];
            sv2[2][row][k] = axx[o];
            sv2[3][row][k] = ayy[o];
            sv2[4][row][k] = axy[o];
        }
    }
    __syncthreads();

    // -------- Phase 3: horizontal conv + SSIM, 256 items ---------------------
    // item = 1 row x 4 output cols (2 packed outputs); 32 rows x 8 colgroups
    float lsum = 0.f;
    {
        const int r  = tid >> 3;
        const int cg = tid & 7;
        const int m0 = 2 * cg;           // packed elems m0 .. m0+6
        u64t acc[5][2];
#pragma unroll
        for (int ch = 0; ch < 5; ch++) {
            const u64t* rowp = &sv2[ch][r][m0];
            u64t E[7];
            ulonglong2 q0 = *(const ulonglong2*)(rowp);
            ulonglong2 q1 = *(const ulonglong2*)(rowp + 2);
            ulonglong2 q2 = *(const ulonglong2*)(rowp + 4);
            E[0] = q0.x; E[1] = q0.y; E[2] = q1.x; E[3] = q1.y;
            E[4] = q2.x; E[5] = q2.y; E[6] = rowp[6];
            float flo[7], fhi[7];
#pragma unroll
            for (int t = 0; t < 7; t++) upk2(E[t], flo[t], fhi[t]);
            u64t O[6];
#pragma unroll
            for (int t = 0; t < 6; t++) O[t] = pk2(fhi[t], flo[t + 1]);
#pragma unroll
            for (int o = 0; o < 2; o++) {
                u64t a = mul2_(wq[WS(0)], E[o]);
#pragma unroll
                for (int j = 1; j < KS; j++) {
                    u64t v = (j & 1) ? O[o + (j - 1) / 2] : E[o + j / 2];
                    a = fma2_(wq[WS(j)], v, a);
                }
                acc[ch][o] = a;
            }
        }
        const u64t TWO = pk2(2.f, 2.f);
        const u64t C1q = pk2(1e-4f, 1e-4f);
        const u64t C2q = pk2(9e-4f, 9e-4f);
#pragma unroll
        for (int o = 0; o < 2; o++) {
            u64t mu1 = acc[0][o], mu2 = acc[1][o];
            u64t mu1sq = mul2_(mu1, mu1);
            u64t mu2sq = mul2_(mu2, mu2);
            u64t mu12  = mul2_(mu1, mu2);
            u64t s1  = sub2_(acc[2][o], mu1sq);
            u64t s2  = sub2_(acc[3][o], mu2sq);
            u64t s12 = sub2_(acc[4][o], mu12);
            u64t num = mul2_(fma2_(TWO, mu12, C1q), fma2_(TWO, s12, C2q));
            u64t den = mul2_(add2_(add2_(mu1sq, mu2sq), C1q),
                             add2_(add2_(s1, s2), C2q));
            float nlo, nhi, dlo, dhi;
            upk2(num, nlo, nhi);
            upk2(den, dlo, dhi);
            lsum += __fdividef(nlo, dlo) + __fdividef(nhi, dhi);
        }
    }

    // -------- Block reduce -> atomic; last block finalizes -------------------
#pragma unroll
    for (int off = 16; off; off >>= 1)
        lsum += __shfl_xor_sync(0xffffffffu, lsum, off);
    if ((tid & 31) == 0) red[tid >> 5] = lsum;
    __syncthreads();
    if (tid == 0) {
        float s = 0.f;
#pragma unroll
        for (int i = 0; i < 8; i++) s += red[i];
        atomicAdd(&g_acc, (double)s);
        __threadfence();
        unsigned int total = gridDim.x * gridDim.y * gridDim.z;
        unsigned int old = atomicAdd(&g_cnt, 1u);
        if (old == total - 1u) {
            double tot = atomicAdd(&g_acc, 0.0);
            out[0] = 1.0f - (float)(tot / 25165824.0);   // 32*3*512*512
            g_acc = 0.0;
            __threadfence();
            g_cnt = 0;
        }
    }
}

extern "C" void kernel_launch(void* const* d_in, const int* in_sizes, int n_in,
                              void* d_out, int out_size) {
    const float* A = (const float*)d_in[0];   // denoised
    const float* B = (const float*)d_in[1];   // clean
    float* out = (float*)d_out;

    dim3 grid(512 / TW, 512 / TH, 32 * 3);    // (16, 16, 96)
    ssim_main_k<<<grid, 256>>>(A, B, out);
}